// round 3
// baseline (speedup 1.0000x reference)
#include <cuda_runtime.h>
#include <stdint.h>

#define N_MAX 50000
#define E_MAX 600000
#define SCAN_BLK 1024
#define NBLK_SCAN ((N_MAX + SCAN_BLK - 1) / SCAN_BLK)   // 49

// Scratch (device globals; no allocation allowed)
__device__ int   g_fmt;                 // 1 = int64 edge_index, 0 = int32
__device__ int   g_src[E_MAX];
__device__ int   g_dst[E_MAX];
__device__ int   g_cnt[N_MAX];
__device__ int   g_off[N_MAX + 1];
__device__ int   g_pos[N_MAX];
__device__ int   g_bsum[NBLK_SCAN + 1];
__device__ float g_dinv[N_MAX];
__device__ int   g_csr[E_MAX];
__device__ float g_h[(size_t)N_MAX * 128];     // x @ W1
__device__ float g_agg[(size_t)N_MAX * 128];   // aggregated layer-1 (relu+bias fused)
__device__ float g_t[(size_t)N_MAX * 64];      // relu_h @ W2

// ---------------------------------------------------------------------------
// dtype detection + edge normalization
// ---------------------------------------------------------------------------
__global__ void k_detect(const int* __restrict__ raw, int E) {
    __shared__ int any_hi;
    if (threadIdx.x == 0) any_hi = 0;
    __syncthreads();
    int samples = E < 4096 ? E : 4096;
    int local = 0;
    for (int i = threadIdx.x; i < samples; i += blockDim.x) {
        // If data is int64, word (2*i+1) is a high word == 0 (values < 2^31).
        // If data is int32, it's a random index, almost surely nonzero somewhere.
        if (raw[2 * i + 1] != 0) local = 1;
    }
    if (local) any_hi = 1;
    __syncthreads();
    if (threadIdx.x == 0) g_fmt = (any_hi == 0) ? 1 : 0;
}

__global__ void k_convert(const int* __restrict__ raw, int E, int n) {
    int e = blockIdx.x * blockDim.x + threadIdx.x;
    if (e >= E) return;
    int fmt = g_fmt;
    int s, d;
    if (fmt) {  // int64: low words at even positions
        s = raw[2 * e];
        d = raw[2 * (E + e)];
    } else {    // int32
        s = raw[e];
        d = raw[E + e];
    }
    s = min(max(s, 0), n - 1);
    d = min(max(d, 0), n - 1);
    g_src[e] = s;
    g_dst[e] = d;
}

// ---------------------------------------------------------------------------
// CSR build
// ---------------------------------------------------------------------------
__global__ void k_cnt_init(int n) {
    int i = blockIdx.x * blockDim.x + threadIdx.x;
    if (i < n) g_cnt[i] = 0;
}

__global__ void k_count(int E) {
    int e = blockIdx.x * blockDim.x + threadIdx.x;
    if (e < E) atomicAdd(&g_cnt[g_dst[e]], 1);
}

// per-block exclusive scan (Hillis-Steele inclusive, then subtract self)
__global__ void __launch_bounds__(SCAN_BLK) k_scan_block(int n) {
    __shared__ int sh[SCAN_BLK];
    int t = threadIdx.x;
    int i = blockIdx.x * SCAN_BLK + t;
    int v = (i < n) ? g_cnt[i] : 0;
    sh[t] = v;
    __syncthreads();
#pragma unroll
    for (int d = 1; d < SCAN_BLK; d <<= 1) {
        int x = (t >= d) ? sh[t - d] : 0;
        __syncthreads();
        sh[t] += x;
        __syncthreads();
    }
    if (i < n) g_off[i] = sh[t] - v;
    if (t == SCAN_BLK - 1) g_bsum[blockIdx.x] = sh[t];
}

__global__ void k_scan_top() {
    if (threadIdx.x == 0) {
        int acc = 0;
        for (int b = 0; b < NBLK_SCAN; b++) {
            int v = g_bsum[b];
            g_bsum[b] = acc;
            acc += v;
        }
    }
}

__global__ void k_scan_add(int n, int E) {
    int i = blockIdx.x * blockDim.x + threadIdx.x;
    if (i < n) {
        int o = g_off[i] + g_bsum[i / SCAN_BLK];
        g_off[i] = o;
        g_pos[i] = o;
        g_dinv[i] = rsqrtf((float)g_cnt[i] + 1.0f);  // +1 self loop
    }
    if (i == 0) g_off[n] = E;
}

__global__ void k_fill(int E) {
    int e = blockIdx.x * blockDim.x + threadIdx.x;
    if (e < E) {
        int p = atomicAdd(&g_pos[g_dst[e]], 1);
        g_csr[p] = g_src[e];
    }
}

// ---------------------------------------------------------------------------
// GEMM: H[n, OUTC] = X[n,128] @ W[128, OUTC]. Block: 32 rows x 64 cols.
// ---------------------------------------------------------------------------
template <int OUTC>
__global__ void __launch_bounds__(256) k_gemm(const float* __restrict__ X,
                                              const float* __restrict__ W,
                                              float* __restrict__ H, int n) {
    __shared__ float Ws[128 * 64];
    const int co = blockIdx.y * 64;
    for (int i = threadIdx.x * 4; i < 128 * 64; i += 256 * 4) {
        int k = i >> 6, j = i & 63;
        *(float4*)&Ws[i] = *(const float4*)&W[k * OUTC + co + j];
    }
    __syncthreads();

    int cg = threadIdx.x & 7;   // 8 col-groups of 8
    int r  = threadIdx.x >> 3;  // 32 rows
    int gr = blockIdx.x * 32 + r;
    if (gr >= n) return;

    const float* xrow = X + (size_t)gr * 128;
    float acc[8] = {0.f, 0.f, 0.f, 0.f, 0.f, 0.f, 0.f, 0.f};
#pragma unroll 4
    for (int k = 0; k < 128; k++) {
        float xv = __ldg(&xrow[k]);
        float4 w0 = *(const float4*)&Ws[k * 64 + cg * 8];
        float4 w1 = *(const float4*)&Ws[k * 64 + cg * 8 + 4];
        acc[0] += xv * w0.x; acc[1] += xv * w0.y;
        acc[2] += xv * w0.z; acc[3] += xv * w0.w;
        acc[4] += xv * w1.x; acc[5] += xv * w1.y;
        acc[6] += xv * w1.z; acc[7] += xv * w1.w;
    }
    float* hrow = H + (size_t)gr * OUTC + co + cg * 8;
    *(float4*)hrow       = make_float4(acc[0], acc[1], acc[2], acc[3]);
    *(float4*)(hrow + 4) = make_float4(acc[4], acc[5], acc[6], acc[7]);
}

// ---------------------------------------------------------------------------
// Aggregation: one warp per dst node, CSR gather, no atomics.
// Fuses self-loop, bias, (relu), store.
// ---------------------------------------------------------------------------
template <int CH, bool RELU>
__global__ void __launch_bounds__(256) k_agg(const float* __restrict__ H,
                                             float* __restrict__ OUT,
                                             const float* __restrict__ bias,
                                             int n) {
    int node = blockIdx.x * 8 + (threadIdx.x >> 5);
    int lane = threadIdx.x & 31;
    if (node >= n) return;

    float di = g_dinv[node];
    int beg = g_off[node];
    int end = g_off[node + 1];

    if (CH == 128) {
        float4 acc = ((const float4*)(H + (size_t)node * 128))[lane];  // self loop
        float ns = di * di;
        acc.x *= ns; acc.y *= ns; acc.z *= ns; acc.w *= ns;
        for (int j = beg; j < end; j++) {
            int s = g_csr[j];
            float nm = g_dinv[s] * di;
            float4 v = ((const float4*)(H + (size_t)s * 128))[lane];
            acc.x += v.x * nm; acc.y += v.y * nm;
            acc.z += v.z * nm; acc.w += v.w * nm;
        }
        int c = lane * 4;
        acc.x += __ldg(&bias[c]);     acc.y += __ldg(&bias[c + 1]);
        acc.z += __ldg(&bias[c + 2]); acc.w += __ldg(&bias[c + 3]);
        if (RELU) {
            acc.x = fmaxf(acc.x, 0.f); acc.y = fmaxf(acc.y, 0.f);
            acc.z = fmaxf(acc.z, 0.f); acc.w = fmaxf(acc.w, 0.f);
        }
        ((float4*)(OUT + (size_t)node * 128))[lane] = acc;
    } else {
        float2 acc = ((const float2*)(H + (size_t)node * 64))[lane];
        float ns = di * di;
        acc.x *= ns; acc.y *= ns;
        for (int j = beg; j < end; j++) {
            int s = g_csr[j];
            float nm = g_dinv[s] * di;
            float2 v = ((const float2*)(H + (size_t)s * 64))[lane];
            acc.x += v.x * nm; acc.y += v.y * nm;
        }
        int c = lane * 2;
        acc.x += __ldg(&bias[c]); acc.y += __ldg(&bias[c + 1]);
        if (RELU) { acc.x = fmaxf(acc.x, 0.f); acc.y = fmaxf(acc.y, 0.f); }
        ((float2*)(OUT + (size_t)node * 64))[lane] = acc;
    }
}

// ---------------------------------------------------------------------------
extern "C" void kernel_launch(void* const* d_in, const int* in_sizes, int n_in,
                              void* d_out, int out_size) {
    const float* x   = (const float*)d_in[0];
    const int*   ei  = (const int*)d_in[1];   // int32 OR int64 (auto-detected)
    const float* W1  = (const float*)d_in[2];
    const float* b1  = (const float*)d_in[3];
    const float* W2  = (const float*)d_in[4];
    const float* b2  = (const float*)d_in[5];
    float*       out = (float*)d_out;

    const int n = in_sizes[0] / 128;
    const int E = in_sizes[1] / 2;

    float* d_h;   cudaGetSymbolAddress((void**)&d_h,   g_h);
    float* d_agg; cudaGetSymbolAddress((void**)&d_agg, g_agg);
    float* d_t;   cudaGetSymbolAddress((void**)&d_t,   g_t);

    const int T = 256;

    // 0) detect edge dtype, normalize to int32 src/dst
    k_detect<<<1, 256>>>(ei, E);
    k_convert<<<(E + T - 1) / T, T>>>(ei, E, n);

    // 1) CSR build + dinv
    k_cnt_init<<<(n + T - 1) / T, T>>>(n);
    k_count<<<(E + T - 1) / T, T>>>(E);
    k_scan_block<<<NBLK_SCAN, SCAN_BLK>>>(n);
    k_scan_top<<<1, 32>>>();
    k_scan_add<<<(n + T - 1) / T, T>>>(n, E);
    k_fill<<<(E + T - 1) / T, T>>>(E);

    // 2) layer 1: h = x @ W1
    {
        dim3 grid((n + 31) / 32, 2);
        k_gemm<128><<<grid, 256>>>(x, W1, d_h, n);
    }

    // 3) aggregate layer 1 (fused self-loop + bias + relu)
    k_agg<128, true><<<(n + 7) / 8, 256>>>(d_h, d_agg, b1, n);

    // 4) layer 2: t = relu_h @ W2
    {
        dim3 grid((n + 31) / 32, 1);
        k_gemm<64><<<grid, 256>>>(d_agg, W2, d_t, n);
    }

    // 5) aggregate layer 2 directly into d_out (fused bias)
    k_agg<64, false><<<(n + 7) / 8, 256>>>(d_t, out, b2, n);
}

// round 4
// speedup vs baseline: 2.8527x; 2.8527x over previous
#include <cuda_runtime.h>
#include <stdint.h>

#define N_MAX 50000
#define E_MAX 600000
#define SCAN_BLK 1024
#define NBLK_SCAN ((N_MAX + SCAN_BLK - 1) / SCAN_BLK)   // 49

// Scratch (device globals; no allocation allowed)
__device__ int   g_fmt;                 // 1 = int64 edge_index, 0 = int32
__device__ int   g_src[E_MAX];
__device__ int   g_dst[E_MAX];
__device__ int   g_cnt[N_MAX];
__device__ int   g_off[N_MAX + 1];
__device__ int   g_pos[N_MAX];
__device__ int   g_bsum[NBLK_SCAN + 1];
__device__ float g_dinv[N_MAX];
__device__ int   g_csr[E_MAX];
__device__ float g_h[(size_t)N_MAX * 128];     // x @ W1
__device__ float g_agg[(size_t)N_MAX * 128];   // aggregated layer-1 (relu+bias fused)
__device__ float g_t[(size_t)N_MAX * 64];      // relu_h @ W2

// ---------------------------------------------------------------------------
// dtype detection + edge normalization
// ---------------------------------------------------------------------------
__global__ void k_detect(const int* __restrict__ raw, int E) {
    __shared__ int any_hi;
    if (threadIdx.x == 0) any_hi = 0;
    __syncthreads();
    int samples = E < 4096 ? E : 4096;
    int local = 0;
    for (int i = threadIdx.x; i < samples; i += blockDim.x) {
        if (raw[2 * i + 1] != 0) local = 1;   // int64 high words are 0
    }
    if (local) any_hi = 1;
    __syncthreads();
    if (threadIdx.x == 0) g_fmt = (any_hi == 0) ? 1 : 0;
}

__global__ void k_convert(const int* __restrict__ raw, int E, int n) {
    int e = blockIdx.x * blockDim.x + threadIdx.x;
    if (e >= E) return;
    int fmt = g_fmt;
    int s, d;
    if (fmt) {  // int64: low words at even positions
        s = raw[2 * e];
        d = raw[2 * (E + e)];
    } else {    // int32
        s = raw[e];
        d = raw[E + e];
    }
    s = min(max(s, 0), n - 1);
    d = min(max(d, 0), n - 1);
    g_src[e] = s;
    g_dst[e] = d;
}

// ---------------------------------------------------------------------------
// CSR build
// ---------------------------------------------------------------------------
__global__ void k_cnt_init(int n) {
    int i = blockIdx.x * blockDim.x + threadIdx.x;
    if (i < n) g_cnt[i] = 0;
}

__global__ void k_count(int E) {
    int e = blockIdx.x * blockDim.x + threadIdx.x;
    if (e < E) atomicAdd(&g_cnt[g_dst[e]], 1);
}

__global__ void __launch_bounds__(SCAN_BLK) k_scan_block(int n) {
    __shared__ int sh[SCAN_BLK];
    int t = threadIdx.x;
    int i = blockIdx.x * SCAN_BLK + t;
    int v = (i < n) ? g_cnt[i] : 0;
    sh[t] = v;
    __syncthreads();
#pragma unroll
    for (int d = 1; d < SCAN_BLK; d <<= 1) {
        int x = (t >= d) ? sh[t - d] : 0;
        __syncthreads();
        sh[t] += x;
        __syncthreads();
    }
    if (i < n) g_off[i] = sh[t] - v;
    if (t == SCAN_BLK - 1) g_bsum[blockIdx.x] = sh[t];
}

__global__ void k_scan_top() {
    if (threadIdx.x == 0) {
        int acc = 0;
        for (int b = 0; b < NBLK_SCAN; b++) {
            int v = g_bsum[b];
            g_bsum[b] = acc;
            acc += v;
        }
    }
}

__global__ void k_scan_add(int n, int E) {
    int i = blockIdx.x * blockDim.x + threadIdx.x;
    if (i < n) {
        int o = g_off[i] + g_bsum[i / SCAN_BLK];
        g_off[i] = o;
        g_pos[i] = o;
        g_dinv[i] = rsqrtf((float)g_cnt[i] + 1.0f);  // +1 self loop
    }
    if (i == 0) g_off[n] = E;
}

__global__ void k_fill(int E) {
    int e = blockIdx.x * blockDim.x + threadIdx.x;
    if (e < E) {
        int p = atomicAdd(&g_pos[g_dst[e]], 1);
        g_csr[p] = g_src[e];
    }
}

// ---------------------------------------------------------------------------
// Register-tiled GEMM: H[n, OUTC] = X[n,128] @ W[128, OUTC].
// Block: 128 rows x 64 cols, 256 threads, 8x4 micro-tile per thread.
// ---------------------------------------------------------------------------
template <int OUTC>
__global__ void __launch_bounds__(256) k_gemm_rt(const float* __restrict__ X,
                                                 const float* __restrict__ W,
                                                 float* __restrict__ H, int n) {
    __shared__ float Xs[16][128];   // k-major
    __shared__ float Ws[16][64];
    const int co   = blockIdx.y * 64;
    const int row0 = blockIdx.x * 128;
    const int tid  = threadIdx.x;
    const int tx   = tid & 15;      // col group: 4 cols
    const int ty   = tid >> 4;      // row group: 8 rows

    float acc[8][4];
#pragma unroll
    for (int i = 0; i < 8; i++)
#pragma unroll
        for (int j = 0; j < 4; j++) acc[i][j] = 0.f;

    for (int k0 = 0; k0 < 128; k0 += 16) {
        // X tile: 128 rows x 16 k = 512 float4 (4 k each)
#pragma unroll
        for (int f = tid; f < 512; f += 256) {
            int r  = f >> 2;
            int kq = f & 3;
            int gr = min(row0 + r, n - 1);
            float4 v = *(const float4*)&X[(size_t)gr * 128 + k0 + kq * 4];
            Xs[kq * 4 + 0][r] = v.x;
            Xs[kq * 4 + 1][r] = v.y;
            Xs[kq * 4 + 2][r] = v.z;
            Xs[kq * 4 + 3][r] = v.w;
        }
        // W tile: 16 k x 64 cols = 256 float4
        {
            int kk = tid >> 4;
            int cq = tid & 15;
            *(float4*)&Ws[kk][cq * 4] =
                *(const float4*)&W[(size_t)(k0 + kk) * OUTC + co + cq * 4];
        }
        __syncthreads();

#pragma unroll
        for (int k = 0; k < 16; k++) {
            float xr[8];
            *(float4*)&xr[0] = *(float4*)&Xs[k][ty * 8];
            *(float4*)&xr[4] = *(float4*)&Xs[k][ty * 8 + 4];
            float4 wv = *(float4*)&Ws[k][tx * 4];
#pragma unroll
            for (int i = 0; i < 8; i++) {
                acc[i][0] += xr[i] * wv.x;
                acc[i][1] += xr[i] * wv.y;
                acc[i][2] += xr[i] * wv.z;
                acc[i][3] += xr[i] * wv.w;
            }
        }
        __syncthreads();
    }

#pragma unroll
    for (int i = 0; i < 8; i++) {
        int gr = row0 + ty * 8 + i;
        if (gr < n)
            *(float4*)&H[(size_t)gr * OUTC + co + tx * 4] = *(float4*)&acc[i][0];
    }
}

// ---------------------------------------------------------------------------
// Aggregation: one warp per dst node, CSR gather, no atomics.
// Fuses self-loop, bias, (relu), store.
// ---------------------------------------------------------------------------
template <int CH, bool RELU>
__global__ void __launch_bounds__(256) k_agg(const float* __restrict__ H,
                                             float* __restrict__ OUT,
                                             const float* __restrict__ bias,
                                             int n) {
    int node = blockIdx.x * 8 + (threadIdx.x >> 5);
    int lane = threadIdx.x & 31;
    if (node >= n) return;

    float di = g_dinv[node];
    int beg = g_off[node];
    int end = g_off[node + 1];

    if (CH == 128) {
        float4 acc = ((const float4*)(H + (size_t)node * 128))[lane];  // self loop
        float ns = di * di;
        acc.x *= ns; acc.y *= ns; acc.z *= ns; acc.w *= ns;
        for (int j = beg; j < end; j++) {
            int s = g_csr[j];
            float nm = g_dinv[s] * di;
            float4 v = ((const float4*)(H + (size_t)s * 128))[lane];
            acc.x += v.x * nm; acc.y += v.y * nm;
            acc.z += v.z * nm; acc.w += v.w * nm;
        }
        int c = lane * 4;
        acc.x += __ldg(&bias[c]);     acc.y += __ldg(&bias[c + 1]);
        acc.z += __ldg(&bias[c + 2]); acc.w += __ldg(&bias[c + 3]);
        if (RELU) {
            acc.x = fmaxf(acc.x, 0.f); acc.y = fmaxf(acc.y, 0.f);
            acc.z = fmaxf(acc.z, 0.f); acc.w = fmaxf(acc.w, 0.f);
        }
        ((float4*)(OUT + (size_t)node * 128))[lane] = acc;
    } else {
        float2 acc = ((const float2*)(H + (size_t)node * 64))[lane];
        float ns = di * di;
        acc.x *= ns; acc.y *= ns;
        for (int j = beg; j < end; j++) {
            int s = g_csr[j];
            float nm = g_dinv[s] * di;
            float2 v = ((const float2*)(H + (size_t)s * 64))[lane];
            acc.x += v.x * nm; acc.y += v.y * nm;
        }
        int c = lane * 2;
        acc.x += __ldg(&bias[c]); acc.y += __ldg(&bias[c + 1]);
        if (RELU) { acc.x = fmaxf(acc.x, 0.f); acc.y = fmaxf(acc.y, 0.f); }
        ((float2*)(OUT + (size_t)node * 64))[lane] = acc;
    }
}

// ---------------------------------------------------------------------------
extern "C" void kernel_launch(void* const* d_in, const int* in_sizes, int n_in,
                              void* d_out, int out_size) {
    const float* x   = (const float*)d_in[0];
    const int*   ei  = (const int*)d_in[1];   // int32 OR int64 (auto-detected)
    const float* W1  = (const float*)d_in[2];
    const float* b1  = (const float*)d_in[3];
    const float* W2  = (const float*)d_in[4];
    const float* b2  = (const float*)d_in[5];
    float*       out = (float*)d_out;

    const int n = in_sizes[0] / 128;
    const int E = in_sizes[1] / 2;

    float* d_h;   cudaGetSymbolAddress((void**)&d_h,   g_h);
    float* d_agg; cudaGetSymbolAddress((void**)&d_agg, g_agg);
    float* d_t;   cudaGetSymbolAddress((void**)&d_t,   g_t);

    const int T = 256;

    // 0) detect edge dtype, normalize to int32 src/dst
    k_detect<<<1, 256>>>(ei, E);
    k_convert<<<(E + T - 1) / T, T>>>(ei, E, n);

    // 1) CSR build + dinv
    k_cnt_init<<<(n + T - 1) / T, T>>>(n);
    k_count<<<(E + T - 1) / T, T>>>(E);
    k_scan_block<<<NBLK_SCAN, SCAN_BLK>>>(n);
    k_scan_top<<<1, 32>>>();
    k_scan_add<<<(n + T - 1) / T, T>>>(n, E);
    k_fill<<<(E + T - 1) / T, T>>>(E);

    // 2) layer 1: h = x @ W1
    {
        dim3 grid((n + 127) / 128, 2);
        k_gemm_rt<128><<<grid, 256>>>(x, W1, d_h, n);
    }

    // 3) aggregate layer 1 (fused self-loop + bias + relu)
    k_agg<128, true><<<(n + 7) / 8, 256>>>(d_h, d_agg, b1, n);

    // 4) layer 2: t = relu_h @ W2
    {
        dim3 grid((n + 127) / 128, 1);
        k_gemm_rt<64><<<grid, 256>>>(d_agg, W2, d_t, n);
    }

    // 5) aggregate layer 2 directly into d_out (fused bias)
    k_agg<64, false><<<(n + 7) / 8, 256>>>(d_t, out, b2, n);
}